// round 1
// baseline (speedup 1.0000x reference)
#include <cuda_runtime.h>

#define NN  192
#define NN2 (NN*NN)
#define NN3 (NN*NN*NN)

// 1/(2*dx) with dx = 1/N
#define INV2DX   96.0f
#define MU_REF_F 1.8e-5f
#define CP_OVER_PR 1395.833333f   // 1005 / 0.72

// Scratch: 6 stress components (t00,t01,t02,t11,t12,t22) + 3 energy-flux comps
__device__ float g_tau[6 * NN3];
__device__ float g_E[3 * NN3];

__device__ __forceinline__ int wrapp(int i) { return (i == NN - 1) ? 0 : i + 1; }
__device__ __forceinline__ int wrapm(int i) { return (i == 0) ? NN - 1 : i - 1; }

// Pass 1: tau_ij and E_j at every grid point
__global__ void __launch_bounds__(NN) pass1_fluxes(const float* __restrict__ u,
                                                   const float* __restrict__ T)
{
    const int x = threadIdx.x;      // axis 2 (contiguous)
    const int y = blockIdx.y;       // axis 1
    const int z = blockIdx.z;       // axis 0
    const int idx = z * NN2 + y * NN + x;

    const int i0p = wrapp(z) * NN2 + y * NN + x;
    const int i0m = wrapm(z) * NN2 + y * NN + x;
    const int i1p = z * NN2 + wrapp(y) * NN + x;
    const int i1m = z * NN2 + wrapm(y) * NN + x;
    const int i2p = z * NN2 + y * NN + wrapp(x);
    const int i2m = z * NN2 + y * NN + wrapm(x);

    float g[3][3];
    float uc[3];
#pragma unroll
    for (int i = 0; i < 3; i++) {
        const float* ui = u + i * NN3;
        uc[i]   = ui[idx];
        g[i][0] = (ui[i0p] - ui[i0m]) * INV2DX;
        g[i][1] = (ui[i1p] - ui[i1m]) * INV2DX;
        g[i][2] = (ui[i2p] - ui[i2m]) * INV2DX;
    }

    const float divu = g[0][0] + g[1][1] + g[2][2];
    const float Tc   = T[idx];
    // mu = MU_REF * (T_dim/T_REF)^0.7 = MU_REF * T^0.7   (T nondimensional)
    const float mu   = MU_REF_F * __powf(Tc, 0.7f);
    const float kk   = mu * CP_OVER_PR;
    const float lam  = -(2.0f / 3.0f) * mu * divu;

    const float t00 = 2.0f * mu * g[0][0] + lam;
    const float t11 = 2.0f * mu * g[1][1] + lam;
    const float t22 = 2.0f * mu * g[2][2] + lam;
    const float t01 = mu * (g[0][1] + g[1][0]);
    const float t02 = mu * (g[0][2] + g[2][0]);
    const float t12 = mu * (g[1][2] + g[2][1]);

    g_tau[0 * NN3 + idx] = t00;
    g_tau[1 * NN3 + idx] = t01;
    g_tau[2 * NN3 + idx] = t02;
    g_tau[3 * NN3 + idx] = t11;
    g_tau[4 * NN3 + idx] = t12;
    g_tau[5 * NN3 + idx] = t22;

    const float gT0 = (T[i0p] - T[i0m]) * INV2DX;
    const float gT1 = (T[i1p] - T[i1m]) * INV2DX;
    const float gT2 = (T[i2p] - T[i2m]) * INV2DX;

    // E_j = k dT/dx_j + sum_i u_i * tau_ij   (energy = div E)
    g_E[0 * NN3 + idx] = kk * gT0 + uc[0] * t00 + uc[1] * t01 + uc[2] * t02;
    g_E[1 * NN3 + idx] = kk * gT1 + uc[0] * t01 + uc[1] * t11 + uc[2] * t12;
    g_E[2 * NN3 + idx] = kk * gT2 + uc[0] * t02 + uc[1] * t12 + uc[2] * t22;
}

// Pass 2: divergences -> [zero, momentum(3), energy]
__global__ void __launch_bounds__(NN) pass2_div(float* __restrict__ out)
{
    const int x = threadIdx.x;
    const int y = blockIdx.y;
    const int z = blockIdx.z;
    const int idx = z * NN2 + y * NN + x;

    const int i0p = wrapp(z) * NN2 + y * NN + x;
    const int i0m = wrapm(z) * NN2 + y * NN + x;
    const int i1p = z * NN2 + wrapp(y) * NN + x;
    const int i1m = z * NN2 + wrapm(y) * NN + x;
    const int i2p = z * NN2 + y * NN + wrapp(x);
    const int i2m = z * NN2 + y * NN + wrapm(x);

    const float* __restrict__ t00 = g_tau + 0 * NN3;
    const float* __restrict__ t01 = g_tau + 1 * NN3;
    const float* __restrict__ t02 = g_tau + 2 * NN3;
    const float* __restrict__ t11 = g_tau + 3 * NN3;
    const float* __restrict__ t12 = g_tau + 4 * NN3;
    const float* __restrict__ t22 = g_tau + 5 * NN3;
    const float* __restrict__ E0  = g_E + 0 * NN3;
    const float* __restrict__ E1  = g_E + 1 * NN3;
    const float* __restrict__ E2  = g_E + 2 * NN3;

    const float mom0 = ((t00[i0p] - t00[i0m]) +
                        (t01[i1p] - t01[i1m]) +
                        (t02[i2p] - t02[i2m])) * INV2DX;
    const float mom1 = ((t01[i0p] - t01[i0m]) +
                        (t11[i1p] - t11[i1m]) +
                        (t12[i2p] - t12[i2m])) * INV2DX;
    const float mom2 = ((t02[i0p] - t02[i0m]) +
                        (t12[i1p] - t12[i1m]) +
                        (t22[i2p] - t22[i2m])) * INV2DX;
    const float en   = ((E0[i0p] - E0[i0m]) +
                        (E1[i1p] - E1[i1m]) +
                        (E2[i2p] - E2[i2m])) * INV2DX;

    out[0 * NN3 + idx] = 0.0f;
    out[1 * NN3 + idx] = mom0;
    out[2 * NN3 + idx] = mom1;
    out[3 * NN3 + idx] = mom2;
    out[4 * NN3 + idx] = en;
}

extern "C" void kernel_launch(void* const* d_in, const int* in_sizes, int n_in,
                              void* d_out, int out_size)
{
    const float* u = (const float*)d_in[0];   // [3, N, N, N]
    const float* T = (const float*)d_in[1];   // [N, N, N]
    float* out = (float*)d_out;               // [5, N, N, N]

    dim3 grid(1, NN, NN);
    dim3 block(NN, 1, 1);
    pass1_fluxes<<<grid, block>>>(u, T);
    pass2_div<<<grid, block>>>(out);
}